// round 1
// baseline (speedup 1.0000x reference)
#include <cuda_runtime.h>
#include <cstdint>

#define Tn 2048
#define KT 48
#define NEGV -10000.0f
#define START_T 46
#define END_T 47

// ---------------- device scratch (static, no allocation) ----------------
__device__ float g_xg[2][Tn][1024];   // per-layer gate preactivations, 2 dirs (16 MB)
__device__ float g_x1[Tn][512];       // layer-0 output / layer-1 input
__device__ float g_x2[Tn][512];       // layer-1 output
__device__ float g_feats[Tn][KT];
__device__ float g_wT[512][KT];       // W_out transposed

// ---------------- gates GEMM: C[dir][m][n] = A[m] . W[n] + bi[n]+bh[n] ----------------
// layer 0: A row = embedding[sentence[sr]], layer 1: A row = g_x1[sr]; sr reversed for dir=1
__global__ __launch_bounds__(256) void gates_gemm(
    const int* __restrict__ sent, const float* __restrict__ emb,
    const float* __restrict__ W, const float* __restrict__ bi,
    const float* __restrict__ bh, int layer)
{
    const int dir = blockIdx.z;
    W  += (size_t)dir * 1024 * 512;
    bi += dir * 1024;
    bh += dir * 1024;

    const int n0 = blockIdx.x * 64;
    const int m0 = blockIdx.y * 64;

    __shared__ __align__(16) float As[16][64];
    __shared__ __align__(16) float Bs[16][64];

    const int tid = threadIdx.x;
    const int tx = tid & 15;
    const int ty = tid >> 4;

    const int lr = tid >> 2;          // 0..63 row in tile
    const int lk = (tid & 3) * 4;     // 0,4,8,12 k in tile

    const int mrow = m0 + lr;
    const int sr = dir ? (Tn - 1 - mrow) : mrow;
    const float* arow;
    if (layer == 0) arow = emb + (size_t)sent[sr] * 512;
    else            arow = &g_x1[sr][0];
    const float* brow = W + (size_t)(n0 + lr) * 512;

    float acc[4][4] = {};

    for (int k0 = 0; k0 < 512; k0 += 16) {
        float4 av = *(const float4*)(arow + k0 + lk);
        float4 bv = *(const float4*)(brow + k0 + lk);
        __syncthreads();
        As[lk + 0][lr] = av.x; As[lk + 1][lr] = av.y;
        As[lk + 2][lr] = av.z; As[lk + 3][lr] = av.w;
        Bs[lk + 0][lr] = bv.x; Bs[lk + 1][lr] = bv.y;
        Bs[lk + 2][lr] = bv.z; Bs[lk + 3][lr] = bv.w;
        __syncthreads();
        #pragma unroll
        for (int k = 0; k < 16; k++) {
            float4 a = *(const float4*)&As[k][ty * 4];
            float4 b = *(const float4*)&Bs[k][tx * 4];
            float am[4] = {a.x, a.y, a.z, a.w};
            float bm[4] = {b.x, b.y, b.z, b.w};
            #pragma unroll
            for (int i = 0; i < 4; i++)
                #pragma unroll
                for (int j = 0; j < 4; j++)
                    acc[i][j] += am[i] * bm[j];
        }
    }
    #pragma unroll
    for (int i = 0; i < 4; i++) {
        int m = m0 + ty * 4 + i;
        #pragma unroll
        for (int j = 0; j < 4; j++) {
            int n = n0 + tx * 4 + j;
            g_xg[dir][m][n] = acc[i][j] + bi[n] + bh[n];
        }
    }
}

// ---------------- LSTM recurrence: cluster of 8 CTAs per direction ----------------
__device__ __forceinline__ float sigf(float x) { return 1.0f / (1.0f + __expf(-x)); }

__global__ void __cluster_dims__(8, 1, 1) __launch_bounds__(512, 1)
lstm_rec(const float* __restrict__ whh, int layer)
{
    const int dir  = blockIdx.x >> 3;
    const int rank = blockIdx.x & 7;
    whh += (size_t)dir * 1024 * 256;
    const float* xg = &g_xg[dir][0][0];

    const int tid  = threadIdx.x;
    const int r    = tid >> 2;            // 0..127 local gate row
    const int q    = tid & 3;             // k-quarter
    const int gate = r >> 5;              // 0..3 (i,f,g,o)
    const int jj   = r & 31;
    const int grow = gate * 256 + rank * 32 + jj;   // global whh row

    // weights resident in registers: 64 fp32 per thread
    float w[64];
    {
        const float4* wp = (const float4*)(whh + (size_t)grow * 256 + q * 64);
        #pragma unroll
        for (int i = 0; i < 16; i++) {
            float4 v = wp[i];
            w[4*i+0] = v.x; w[4*i+1] = v.y; w[4*i+2] = v.z; w[4*i+3] = v.w;
        }
    }

    __shared__ __align__(16) float hbuf[2][256];
    __shared__ float gs[128];
    if (tid < 256) hbuf[0][tid] = 0.0f;
    __syncthreads();

    uint32_t haddr0 = 0;
    if (tid < 32)
        haddr0 = (uint32_t)__cvta_generic_to_shared(&hbuf[0][rank * 32 + tid]);

    float c = 0.0f;
    float xgv = 0.0f;
    if (q == 0) xgv = __ldg(xg + grow);

    for (int s = 0; s < Tn; ++s) {
        // prefetch next step's xg (hide L2 latency)
        float xgn = 0.0f;
        if (q == 0) {
            int sn = s + 1; if (sn >= Tn) sn = Tn - 1;
            xgn = __ldg(xg + (size_t)sn * 1024 + grow);
        }
        const float* h = hbuf[s & 1] + q * 64;
        float a0 = 0.f, a1 = 0.f, a2 = 0.f, a3 = 0.f;
        #pragma unroll
        for (int i = 0; i < 16; i++) {
            float4 hv = ((const float4*)h)[i];
            a0 += w[4*i+0] * hv.x;
            a1 += w[4*i+1] * hv.y;
            a2 += w[4*i+2] * hv.z;
            a3 += w[4*i+3] * hv.w;
        }
        float acc = (a0 + a1) + (a2 + a3);
        acc += __shfl_xor_sync(0xffffffffu, acc, 1);
        acc += __shfl_xor_sync(0xffffffffu, acc, 2);
        if (q == 0) gs[r] = acc + xgv;
        xgv = xgn;
        __syncthreads();
        if (tid < 32) {
            float gi = gs[tid];
            float gf = gs[32 + tid];
            float gg = gs[64 + tid];
            float go = gs[96 + tid];
            c = sigf(gf) * c + sigf(gi) * tanhf(gg);
            float hn = sigf(go) * tanhf(c);
            int t = dir ? (Tn - 1 - s) : s;
            float* xo = layer ? &g_x2[0][0] : &g_x1[0][0];
            xo[(size_t)t * 512 + dir * 256 + rank * 32 + tid] = hn;
            // broadcast new h to all CTAs' next buffer via DSMEM
            uint32_t dst = haddr0 + ((s + 1) & 1) * 1024;
            #pragma unroll
            for (int tc = 0; tc < 8; ++tc) {
                uint32_t remote;
                asm volatile("mapa.shared::cluster.u32 %0, %1, %2;"
                             : "=r"(remote) : "r"(dst), "r"(tc));
                asm volatile("st.shared::cluster.f32 [%0], %1;"
                             :: "r"(remote), "f"(hn) : "memory");
            }
        }
        asm volatile("barrier.cluster.arrive.aligned;" ::: "memory");
        asm volatile("barrier.cluster.wait.aligned;"   ::: "memory");
    }
}

// ---------------- W_out transpose ----------------
__global__ void wout_transpose(const float* __restrict__ W)
{
    int idx = blockIdx.x * 256 + threadIdx.x;     // 48*512
    if (idx < KT * 512) {
        int j = idx / 512, k = idx % 512;
        g_wT[k][j] = W[idx];
    }
}

// ---------------- feats = x2 @ W_out^T + b_out ----------------
__global__ __launch_bounds__(64) void feats_kernel(const float* __restrict__ bout)
{
    int row = blockIdx.x;
    __shared__ __align__(16) float xs[512];
    int tid = threadIdx.x;
    #pragma unroll
    for (int i = 0; i < 2; i++)
        ((float4*)xs)[tid * 2 + i] = ((const float4*)&g_x2[row][0])[tid * 2 + i];
    __syncthreads();
    if (tid < KT) {
        float a0 = 0.f, a1 = 0.f, a2 = 0.f, a3 = 0.f;
        #pragma unroll 4
        for (int k = 0; k < 512; k += 4) {
            a0 += xs[k + 0] * g_wT[k + 0][tid];
            a1 += xs[k + 1] * g_wT[k + 1][tid];
            a2 += xs[k + 2] * g_wT[k + 2][tid];
            a3 += xs[k + 3] * g_wT[k + 3][tid];
        }
        g_feats[row][tid] = (a0 + a1) + (a2 + a3) + bout[tid];
    }
}

// ---------------- Viterbi (single CTA, backpointers in smem) ----------------
__global__ __launch_bounds__(64) void viterbi(const float* __restrict__ trans,
                                              float* __restrict__ out, int out_size)
{
    extern __shared__ unsigned char sm[];
    unsigned char* bp = sm;                       // Tn*KT bytes
    float* fv = (float*)(sm + Tn * KT);           // 2*KT ping-pong
    const int j = threadIdx.x;

    float tr[KT];
    if (j < KT) {
        #pragma unroll
        for (int p = 0; p < KT; p++) tr[p] = trans[j * KT + p];
        fv[j] = (j == START_T) ? 0.0f : NEGV;
    }
    __syncthreads();

    for (int t = 0; t < Tn; ++t) {
        const float* fcur = fv + (t & 1) * KT;
        float* fnxt = fv + ((t + 1) & 1) * KT;
        if (j < KT) {
            float best = -3.4e38f; int arg = 0;
            #pragma unroll
            for (int p = 0; p < KT; p++) {
                float s = fcur[p] + tr[p];
                if (s > best) { best = s; arg = p; }   // strict > : first max, matches jnp.argmax
            }
            fnxt[j] = best + g_feats[t][j];
            bp[t * KT + j] = (unsigned char)arg;
        }
        __syncthreads();
    }

    __shared__ float term[KT];
    if (j < KT) term[j] = fv[(Tn & 1) * KT + j] + trans[END_T * KT + j];
    __syncthreads();

    if (j == 0) {
        float best = -3.4e38f; int arg = 0;
        for (int p = 0; p < KT; p++)
            if (term[p] > best) { best = term[p]; arg = p; }

        int off = 0;
        if (out_size >= Tn + 1) { out[0] = best; off = 1; }
        else if (out_size == 1) { out[0] = best; }
        if (out_size >= Tn) {
            int cur = arg;
            for (int t = Tn - 1; t >= 0; --t) {
                out[off + t] = (float)cur;
                cur = bp[t * KT + cur];
            }
        }
    }
}

// ---------------- launch ----------------
extern "C" void kernel_launch(void* const* d_in, const int* in_sizes, int n_in,
                              void* d_out, int out_size)
{
    const int*   sent  = (const int*)  d_in[0];
    const float* emb   = (const float*)d_in[1];
    const float* wih   = (const float*)d_in[2];
    const float* whh   = (const float*)d_in[3];
    const float* bih   = (const float*)d_in[4];
    const float* bhh   = (const float*)d_in[5];
    const float* wout  = (const float*)d_in[6];
    const float* bout  = (const float*)d_in[7];
    const float* trans = (const float*)d_in[8];
    float* out = (float*)d_out;

    const int vit_smem = Tn * KT + 2 * KT * 4 + 16;
    cudaFuncSetAttribute(viterbi, cudaFuncAttributeMaxDynamicSharedMemorySize, vit_smem);

    dim3 ggrid(16, 32, 2);   // N/64, M/64, dirs

    // layer 0
    gates_gemm<<<ggrid, 256>>>(sent, emb, wih, bih, bhh, 0);
    lstm_rec<<<16, 512>>>(whh, 0);
    // layer 1
    gates_gemm<<<ggrid, 256>>>(sent, emb, wih + 2 * 1024 * 512, bih + 2 * 1024, bhh + 2 * 1024, 1);
    lstm_rec<<<16, 512>>>(whh + 2 * 1024 * 256, 1);
    // output projection + viterbi
    wout_transpose<<<96, 256>>>(wout);
    feats_kernel<<<Tn, 64>>>(bout);
    viterbi<<<1, 64, vit_smem>>>(trans, out, out_size);
}